// round 7
// baseline (speedup 1.0000x reference)
#include <cuda_runtime.h>
#include <cuda_fp16.h>
#include <cstdint>
#include <cstddef>

#define NE 8
#define NC 4096
#define ND 1024
#define NF 4096

// Device scratch (no allocs allowed)
__device__ __half g_Xh [(size_t)NE * NC * ND];   // X fp16
__device__ __half g_W1h[(size_t)NE * ND * NF];   // W1 fp16 (natural [D,F])
__device__ __half g_W2h[(size_t)NE * NF * ND];   // W2 fp16 (natural [F,D])
__device__ __half g_Hh [(size_t)NE * NC * NF];   // relu(X@W1) fp16

// ---------------- helpers ----------------
__device__ __forceinline__ uint32_t smem_u32(const void* p) {
    uint32_t a;
    asm("{ .reg .u64 t; cvta.to.shared.u64 t, %1; cvt.u32.u64 %0, t; }" : "=r"(a) : "l"(p));
    return a;
}
__device__ __forceinline__ void cp_async16(uint32_t dst, const void* src) {
    asm volatile("cp.async.cg.shared.global [%0], [%1], 16;" :: "r"(dst), "l"(src));
}
#define CP_COMMIT() asm volatile("cp.async.commit_group;" ::: "memory")
#define CP_WAIT1()  asm volatile("cp.async.wait_group 1;" ::: "memory")

__device__ __forceinline__ void ldmx4(uint32_t r[4], uint32_t addr) {
    asm volatile("ldmatrix.sync.aligned.m8n8.x4.shared.b16 {%0,%1,%2,%3}, [%4];"
        : "=r"(r[0]), "=r"(r[1]), "=r"(r[2]), "=r"(r[3]) : "r"(addr));
}
__device__ __forceinline__ void ldmx4t(uint32_t r[4], uint32_t addr) {
    asm volatile("ldmatrix.sync.aligned.m8n8.x4.trans.shared.b16 {%0,%1,%2,%3}, [%4];"
        : "=r"(r[0]), "=r"(r[1]), "=r"(r[2]), "=r"(r[3]) : "r"(addr));
}
__device__ __forceinline__ void mma_f16(float d[4],
                                        uint32_t a0, uint32_t a1, uint32_t a2, uint32_t a3,
                                        uint32_t b0, uint32_t b1) {
    asm volatile("mma.sync.aligned.m16n8k16.row.col.f32.f16.f16.f32 "
        "{%0,%1,%2,%3}, {%4,%5,%6,%7}, {%8,%9}, {%0,%1,%2,%3};"
        : "+f"(d[0]), "+f"(d[1]), "+f"(d[2]), "+f"(d[3])
        : "r"(a0), "r"(a1), "r"(a2), "r"(a3), "r"(b0), "r"(b1));
}

// ---------------- prep: f32 -> f16 cast ----------------
__global__ void f32_to_f16_kernel(const float* __restrict__ in, __half* __restrict__ out, size_t n4) {
    size_t i = (size_t)blockIdx.x * blockDim.x + threadIdx.x;
    if (i >= n4) return;
    float4 v = reinterpret_cast<const float4*>(in)[i];
    __half2 h0 = __floats2half2_rn(v.x, v.y);
    __half2 h1 = __floats2half2_rn(v.z, v.w);
    uint2 o;
    o.x = *reinterpret_cast<uint32_t*>(&h0);
    o.y = *reinterpret_cast<uint32_t*>(&h1);
    reinterpret_cast<uint2*>(out)[i] = o;
}

// ---------------- fp16 mma.sync GEMM ----------------
// C[M,N] = A[M,K] (K-major) * B[K,N] (N-major), batched over blockIdx.z.
// CTA 128x128, BK=64 (4 k16 phases/iter), 3-stage cp.async, 2 CTAs/SM,
// fragment double-buffering across phases. 8 warps; warp tile 64x32.
#define STAGES 3
#define BK 64
#define TILE_M 128
#define TILE_N 128
#define AROWB 144                    // 128B data + 16 pad per A row (128 rows)
#define BROWB 272                    // 256B data + 16 pad per B k-row (64 rows)
#define STG_A (TILE_M * AROWB)       // 18432 B
#define STG_B (BK * BROWB)           // 17408 B
#define SM_TOTAL (STAGES * (STG_A + STG_B))   // 107520 B -> 2 CTAs/SM

#define LDM_A(dst, base, p) do {                                              \
    _Pragma("unroll")                                                         \
    for (int _mt = 0; _mt < 4; _mt++)                                         \
        ldmx4((dst)[_mt], (base) + a_lm + _mt * (16 * AROWB) + (p) * 32);     \
} while (0)
#define LDM_B(dst, base, p) do {                                              \
    _Pragma("unroll")                                                         \
    for (int _np = 0; _np < 2; _np++)                                         \
        ldmx4t((dst)[_np], (base) + b_lm + (p) * (16 * BROWB) + _np * 32);    \
} while (0)
#define MMA_ALL(af, bf) do {                                                  \
    _Pragma("unroll")                                                         \
    for (int _mt = 0; _mt < 4; _mt++) {                                       \
        _Pragma("unroll")                                                     \
        for (int _nt = 0; _nt < 4; _nt++) {                                   \
            const uint32_t* _b = (bf)[_nt >> 1];                              \
            mma_f16(acc[_mt][_nt], (af)[_mt][0], (af)[_mt][1],                \
                    (af)[_mt][2], (af)[_mt][3],                               \
                    (_nt & 1) ? _b[2] : _b[0], (_nt & 1) ? _b[3] : _b[1]);    \
        }                                                                     \
    }                                                                         \
} while (0)

template<bool RELU, bool OUT_HALF>
__global__ __launch_bounds__(256, 2)
void gemm_f16_mma(const __half* __restrict__ A, const __half* __restrict__ B,
                  void* __restrict__ Cv,
                  int K, int lda, int ldb, int ldc,
                  long long sA, long long sB, long long sC)
{
    extern __shared__ char smem[];
    const uint32_t a_base = smem_u32(smem);
    const uint32_t b_base = a_base + STAGES * STG_A;

    const int tid = threadIdx.x;
    const int wid = tid >> 5;
    const int lane = tid & 31;
    const int lq = lane >> 2;
    const int lr = lane & 3;
    const int warpM = wid & 1;
    const int warpN = wid >> 1;

    const long long e = blockIdx.z;
    const __half* Ag = A + e * sA + (long long)blockIdx.y * TILE_M * lda;
    const __half* Bg = B + e * sB + (long long)blockIdx.x * TILE_N;   // B: [K,N]

    // cp.async: A 1024 chunks/stage, B 1024 chunks/stage; 4 per thread each.
    uint32_t a_dst[4], b_dst[4], a_off[4], b_off[4];
    #pragma unroll
    for (int j = 0; j < 4; j++) {
        int g = tid + 256 * j;
        int ar = g >> 3, as = g & 7;               // A: row 0..127, seg 0..7
        a_dst[j] = ar * AROWB + as * 16;
        a_off[j] = (uint32_t)(ar * lda + as * 8);  // + k0 per stage
        int br = g >> 4, bc = g & 15;              // B: k-row 0..63, col 0..15
        b_dst[j] = br * BROWB + bc * 16;
        b_off[j] = (uint32_t)(br * ldb + bc * 8);  // + k0*ldb per stage
    }

    // ldmatrix source offsets (both strides ≡16 mod 128 -> conflict-free)
    const uint32_t a_lm = (uint32_t)(warpM * 64 + (lane & 15)) * AROWB + ((lane >> 4) & 1) * 16;
    const uint32_t b_lm = (uint32_t)(lane & 15) * BROWB
                        + (uint32_t)(warpN * 32 + ((lane >> 4) & 1) * 8) * 2;

    const int niters = K / BK;

    // prologue: stages 0,1
    #pragma unroll
    for (int s = 0; s < STAGES - 1; s++) {
        const uint32_t ao = a_base + s * STG_A;
        const uint32_t bo = b_base + s * STG_B;
        const uint32_t ka = (uint32_t)(s * BK);
        const uint32_t kb = ka * (uint32_t)ldb;
        #pragma unroll
        for (int j = 0; j < 4; j++) cp_async16(ao + a_dst[j], Ag + a_off[j] + ka);
        #pragma unroll
        for (int j = 0; j < 4; j++) cp_async16(bo + b_dst[j], Bg + b_off[j] + kb);
        CP_COMMIT();
    }

    float acc[4][4][4];
    #pragma unroll
    for (int i = 0; i < 4; i++)
        #pragma unroll
        for (int j = 0; j < 4; j++)
            #pragma unroll
            for (int k = 0; k < 4; k++)
                acc[i][j][k] = 0.0f;

    uint32_t afX[4][4], bfX[2][4];   // even phases
    uint32_t afY[4][4], bfY[2][4];   // odd phases

    // wait stage 0, load phase-0 frags
    CP_WAIT1();
    __syncthreads();
    uint32_t As = a_base, Bs = b_base;           // current stage
    uint32_t pA = a_base + 2 * STG_A;            // prefetch slot (stage 2)
    uint32_t pB = b_base + 2 * STG_B;
    LDM_A(afX, As, 0);
    LDM_B(bfX, Bs, 0);

    int pre = STAGES - 1;

    for (int it = 0; it < niters; it++) {
        // ---- phase 0: load p1 frags, prefetch gmem stage it+2, MMA p0 ----
        LDM_A(afY, As, 1);
        LDM_B(bfY, Bs, 1);
        if (pre < niters) {
            const uint32_t ka = (uint32_t)(pre * BK);
            const uint32_t kb = ka * (uint32_t)ldb;
            #pragma unroll
            for (int j = 0; j < 4; j++) cp_async16(pA + a_dst[j], Ag + a_off[j] + ka);
            #pragma unroll
            for (int j = 0; j < 4; j++) cp_async16(pB + b_dst[j], Bg + b_off[j] + kb);
            pA += STG_A; if (pA == a_base + STAGES * STG_A) pA = a_base;
            pB += STG_B; if (pB == b_base + STAGES * STG_B) pB = b_base;
        }
        CP_COMMIT();
        pre++;
        MMA_ALL(afX, bfX);

        // ---- phase 1: load p2, MMA p1 ----
        LDM_A(afX, As, 2);
        LDM_B(bfX, Bs, 2);
        MMA_ALL(afY, bfY);

        // ---- phase 2: load p3, MMA p2 ----
        LDM_A(afY, As, 3);
        LDM_B(bfY, Bs, 3);
        MMA_ALL(afX, bfX);

        // ---- phase 3: advance stage, load next p0, MMA p3 ----
        if (it + 1 < niters) {
            CP_WAIT1();          // stage it+1 landed (<=1 group in flight)
            __syncthreads();     // all reads of the recycled slot are done
            As += STG_A; if (As == a_base + STAGES * STG_A) As = a_base;
            Bs += STG_B; if (Bs == b_base + STAGES * STG_B) Bs = b_base;
            LDM_A(afX, As, 0);
            LDM_B(bfX, Bs, 0);
        }
        MMA_ALL(afY, bfY);
    }

    // ---- epilogue ----
    #pragma unroll
    for (int mt = 0; mt < 4; mt++) {
        const int r0 = blockIdx.y * TILE_M + warpM * 64 + mt * 16 + lq;
        #pragma unroll
        for (int nt = 0; nt < 4; nt++) {
            const int c0 = blockIdx.x * TILE_N + warpN * 32 + nt * 8 + 2 * lr;
            float v0 = acc[mt][nt][0], v1 = acc[mt][nt][1];
            float v2 = acc[mt][nt][2], v3 = acc[mt][nt][3];
            if (RELU) {
                v0 = fmaxf(v0, 0.0f); v1 = fmaxf(v1, 0.0f);
                v2 = fmaxf(v2, 0.0f); v3 = fmaxf(v3, 0.0f);
            }
            if (OUT_HALF) {
                __half* C = (__half*)Cv + e * sC;
                *reinterpret_cast<__half2*>(C + (long long)r0 * ldc + c0)       = __floats2half2_rn(v0, v1);
                *reinterpret_cast<__half2*>(C + (long long)(r0 + 8) * ldc + c0) = __floats2half2_rn(v2, v3);
            } else {
                float* C = (float*)Cv + e * sC;
                *reinterpret_cast<float2*>(C + (long long)r0 * ldc + c0)       = make_float2(v0, v1);
                *reinterpret_cast<float2*>(C + (long long)(r0 + 8) * ldc + c0) = make_float2(v2, v3);
            }
        }
    }
}

// ---------------- launch ----------------
extern "C" void kernel_launch(void* const* d_in, const int* in_sizes, int n_in,
                              void* d_out, int out_size)
{
    const float* X  = (const float*)d_in[0];
    const float* W1 = (const float*)d_in[2];
    const float* W2 = (const float*)d_in[3];
    float* Y = (float*)d_out;

    __half *Xh, *W1h, *W2h, *Hh;
    cudaGetSymbolAddress((void**)&Xh,  g_Xh);
    cudaGetSymbolAddress((void**)&W1h, g_W1h);
    cudaGetSymbolAddress((void**)&W2h, g_W2h);
    cudaGetSymbolAddress((void**)&Hh,  g_Hh);

    static bool attr_set = false;
    if (!attr_set) {
        cudaFuncSetAttribute(gemm_f16_mma<true, true>,   cudaFuncAttributeMaxDynamicSharedMemorySize, SM_TOTAL);
        cudaFuncSetAttribute(gemm_f16_mma<false, false>, cudaFuncAttributeMaxDynamicSharedMemorySize, SM_TOTAL);
        attr_set = true;
    }

    // casts
    {
        size_t n4 = (size_t)NE * NC * ND / 4;
        f32_to_f16_kernel<<<(unsigned)((n4 + 255) / 256), 256>>>(X, Xh, n4);
    }
    {
        size_t n4 = (size_t)NE * ND * NF / 4;
        f32_to_f16_kernel<<<(unsigned)((n4 + 255) / 256), 256>>>(W1, W1h, n4);
    }
    {
        size_t n4 = (size_t)NE * NF * ND / 4;
        f32_to_f16_kernel<<<(unsigned)((n4 + 255) / 256), 256>>>(W2, W2h, n4);
    }

    // GEMM1: H = relu(Xh @ W1h); M=C, N=F, K=D; ldb=NF
    {
        dim3 g(NF / TILE_N, NC / TILE_M, NE);
        gemm_f16_mma<true, true><<<g, 256, SM_TOTAL>>>(
            Xh, W1h, Hh,
            ND, ND, NF, NF,
            (long long)NC * ND, (long long)ND * NF, (long long)NC * NF);
    }
    // GEMM2: Y = H @ W2h; M=C, N=D, K=F; ldb=ND
    {
        dim3 g(ND / TILE_N, NC / TILE_M, NE);
        gemm_f16_mma<false, false><<<g, 256, SM_TOTAL>>>(
            Hh, W2h, Y,
            NF, NF, ND, ND,
            (long long)NC * NF, (long long)NF * ND, (long long)NC * ND);
    }
}

// round 8
// speedup vs baseline: 1.2679x; 1.2679x over previous
#include <cuda_runtime.h>
#include <cuda_fp16.h>
#include <cstdint>
#include <cstddef>

#define NE 8
#define NC 4096
#define ND 1024
#define NF 4096

// Device scratch (no allocs allowed)
__device__ __half g_Xh [(size_t)NE * NC * ND];   // X fp16
__device__ __half g_W1h[(size_t)NE * ND * NF];   // W1 fp16 (natural [D,F])
__device__ __half g_W2h[(size_t)NE * NF * ND];   // W2 fp16 (natural [F,D])
__device__ __half g_Hh [(size_t)NE * NC * NF];   // relu(X@W1) fp16

// ---------------- helpers ----------------
__device__ __forceinline__ uint32_t smem_u32(const void* p) {
    uint32_t a;
    asm("{ .reg .u64 t; cvta.to.shared.u64 t, %1; cvt.u32.u64 %0, t; }" : "=r"(a) : "l"(p));
    return a;
}
__device__ __forceinline__ void cp_async16(uint32_t dst, const void* src) {
    asm volatile("cp.async.cg.shared.global [%0], [%1], 16;" :: "r"(dst), "l"(src));
}
#define CP_COMMIT() asm volatile("cp.async.commit_group;" ::: "memory")
#define CP_WAIT2()  asm volatile("cp.async.wait_group 2;" ::: "memory")

__device__ __forceinline__ void ldmx4(uint32_t r[4], uint32_t addr) {
    asm volatile("ldmatrix.sync.aligned.m8n8.x4.shared.b16 {%0,%1,%2,%3}, [%4];"
        : "=r"(r[0]), "=r"(r[1]), "=r"(r[2]), "=r"(r[3]) : "r"(addr));
}
__device__ __forceinline__ void ldmx4t(uint32_t r[4], uint32_t addr) {
    asm volatile("ldmatrix.sync.aligned.m8n8.x4.trans.shared.b16 {%0,%1,%2,%3}, [%4];"
        : "=r"(r[0]), "=r"(r[1]), "=r"(r[2]), "=r"(r[3]) : "r"(addr));
}
__device__ __forceinline__ void mma_f16(float d[4],
                                        uint32_t a0, uint32_t a1, uint32_t a2, uint32_t a3,
                                        uint32_t b0, uint32_t b1) {
    asm volatile("mma.sync.aligned.m16n8k16.row.col.f32.f16.f16.f32 "
        "{%0,%1,%2,%3}, {%4,%5,%6,%7}, {%8,%9}, {%0,%1,%2,%3};"
        : "+f"(d[0]), "+f"(d[1]), "+f"(d[2]), "+f"(d[3])
        : "r"(a0), "r"(a1), "r"(a2), "r"(a3), "r"(b0), "r"(b1));
}

// ---------------- prep: f32 -> f16 cast ----------------
__global__ void f32_to_f16_kernel(const float* __restrict__ in, __half* __restrict__ out, size_t n4) {
    size_t i = (size_t)blockIdx.x * blockDim.x + threadIdx.x;
    if (i >= n4) return;
    float4 v = reinterpret_cast<const float4*>(in)[i];
    __half2 h0 = __floats2half2_rn(v.x, v.y);
    __half2 h1 = __floats2half2_rn(v.z, v.w);
    uint2 o;
    o.x = *reinterpret_cast<uint32_t*>(&h0);
    o.y = *reinterpret_cast<uint32_t*>(&h1);
    reinterpret_cast<uint2*>(out)[i] = o;
}

// ---------------- fp16 mma.sync GEMM (R6 structure, compile-time shapes) ----
// C[M,N] = A[M,K] (K-major) * B[K,N] (N-major), batched over blockIdx.z.
// CTA 128x128, BK=32, 4-stage cp.async, 2 CTAs/SM, fragment double-buffering.
// 8 warps: warpM = wid&1, warpN = wid>>1; warp tile 64x32.
#define STAGES 4
#define BK 32
#define TILE_M 128
#define TILE_N 128
#define AROWB 80                     // A smem: 64B data + 16 pad per row (128 rows)
#define BROWB 272                    // B smem: 256B data + 16 pad per k-row (32 rows)
#define STG_A (TILE_M * AROWB)       // 10240 B
#define STG_B (BK * BROWB)           // 8704 B
#define SM_TOTAL (STAGES * (STG_A + STG_B))   // 75776 B -> 2 CTAs/SM

template<bool RELU, bool OUT_HALF, int K, int LDA, int LDB, int LDC>
__global__ __launch_bounds__(256, 2)
void gemm_f16_mma(const __half* __restrict__ A, const __half* __restrict__ B,
                  void* __restrict__ Cv)
{
    constexpr long long SA = (long long)NC * LDA;
    constexpr long long SB = (long long)K * LDB;
    constexpr long long SC = (long long)NC * LDC;
    constexpr int NITERS = K / BK;

    extern __shared__ char smem[];
    const uint32_t a_base = smem_u32(smem);
    const uint32_t b_base = a_base + STAGES * STG_A;

    const int tid = threadIdx.x;
    const int wid = tid >> 5;
    const int lane = tid & 31;
    const int lq = lane >> 2;
    const int lr = lane & 3;
    const int warpM = wid & 1;
    const int warpN = wid >> 1;

    const long long e = blockIdx.z;
    const __half* Ag = A + e * SA + (long long)blockIdx.y * TILE_M * LDA;
    const __half* Bg = B + e * SB + (long long)blockIdx.x * TILE_N;   // B: [K,N]

    // cp.async slots (512 chunks of 16B per matrix per stage; 2 per thread each)
    uint32_t a_dst[2], b_dst[2], a_off[2], b_off[2];
    #pragma unroll
    for (int j = 0; j < 2; j++) {
        int g = tid + 256 * j;
        int ar = g >> 2, as = g & 3;
        a_dst[j] = ar * AROWB + as * 16;
        a_off[j] = (uint32_t)(ar * LDA + as * 8);
        int br = g >> 4, bc = g & 15;
        b_dst[j] = br * BROWB + bc * 16;
        b_off[j] = (uint32_t)(br * LDB + bc * 8);
    }

    // ldmatrix source offsets (strides ≡16 mod 128 -> conflict-free)
    const uint32_t a_lm = (uint32_t)(warpM * 64 + (lane & 15)) * AROWB + ((lane >> 4) & 1) * 16;
    const uint32_t b_lm = (uint32_t)(lane & 15) * BROWB
                        + (uint32_t)(warpN * 32 + ((lane >> 4) & 1) * 8) * 2;

    // prologue: stages 0..2
    #pragma unroll
    for (int s = 0; s < STAGES - 1; s++) {
        const uint32_t ao = a_base + s * STG_A;
        const uint32_t bo = b_base + s * STG_B;
        constexpr uint32_t dummy = 0; (void)dummy;
        const uint32_t ka = (uint32_t)(s * BK);
        const uint32_t kb = ka * (uint32_t)LDB;
        #pragma unroll
        for (int j = 0; j < 2; j++) cp_async16(ao + a_dst[j], Ag + a_off[j] + ka);
        #pragma unroll
        for (int j = 0; j < 2; j++) cp_async16(bo + b_dst[j], Bg + b_off[j] + kb);
        CP_COMMIT();
    }

    float acc[4][4][4];
    #pragma unroll
    for (int i = 0; i < 4; i++)
        #pragma unroll
        for (int j = 0; j < 4; j++)
            #pragma unroll
            for (int k = 0; k < 4; k++)
                acc[i][j][k] = 0.0f;

    uint32_t afc[4][4], bfc[2][4];   // kk=0 frags
    uint32_t afn[4][4], bfn[2][4];   // kk=1 frags

    // wait stage 0, load kk=0 frags
    CP_WAIT2();
    __syncthreads();
    #pragma unroll
    for (int mt = 0; mt < 4; mt++) ldmx4(afc[mt], a_base + a_lm + mt * (16 * AROWB));
    #pragma unroll
    for (int np = 0; np < 2; np++) ldmx4t(bfc[np], b_base + b_lm + np * 32);

    int pre = STAGES - 1;

    for (int it = 0; it < NITERS; it++) {
        const int buf = it & (STAGES - 1);
        const uint32_t As = a_base + buf * STG_A;
        const uint32_t Bs = b_base + buf * STG_B;

        // ---- phase kk=0: load kk=1 frags, prefetch gmem, MMA on cur ----
        #pragma unroll
        for (int mt = 0; mt < 4; mt++) ldmx4(afn[mt], As + a_lm + mt * (16 * AROWB) + 32);
        #pragma unroll
        for (int np = 0; np < 2; np++) ldmx4t(bfn[np], Bs + b_lm + 16 * BROWB + np * 32);

        if (pre < NITERS) {
            const int lb = pre & (STAGES - 1);
            const uint32_t ao = a_base + lb * STG_A;
            const uint32_t bo = b_base + lb * STG_B;
            const uint32_t ka = (uint32_t)(pre * BK);
            const uint32_t kb = ka * (uint32_t)LDB;
            #pragma unroll
            for (int j = 0; j < 2; j++) cp_async16(ao + a_dst[j], Ag + a_off[j] + ka);
            #pragma unroll
            for (int j = 0; j < 2; j++) cp_async16(bo + b_dst[j], Bg + b_off[j] + kb);
        }
        CP_COMMIT();
        pre++;

        #pragma unroll
        for (int mt = 0; mt < 4; mt++)
            #pragma unroll
            for (int nt = 0; nt < 4; nt++) {
                const uint32_t* b = bfc[nt >> 1];
                mma_f16(acc[mt][nt], afc[mt][0], afc[mt][1], afc[mt][2], afc[mt][3],
                        (nt & 1) ? b[2] : b[0], (nt & 1) ? b[3] : b[1]);
            }

        // ---- phase kk=1: advance smem stage, load next kk=0 frags, MMA on nxt ----
        if (it + 1 < NITERS) {
            CP_WAIT2();          // stage it+1 landed
            __syncthreads();     // all reads of the slot the next prefetch overwrites are done
            const int nb = (it + 1) & (STAGES - 1);
            const uint32_t As2 = a_base + nb * STG_A;
            const uint32_t Bs2 = b_base + nb * STG_B;
            #pragma unroll
            for (int mt = 0; mt < 4; mt++) ldmx4(afc[mt], As2 + a_lm + mt * (16 * AROWB));
            #pragma unroll
            for (int np = 0; np < 2; np++) ldmx4t(bfc[np], Bs2 + b_lm + np * 32);
        }

        #pragma unroll
        for (int mt = 0; mt < 4; mt++)
            #pragma unroll
            for (int nt = 0; nt < 4; nt++) {
                const uint32_t* b = bfn[nt >> 1];
                mma_f16(acc[mt][nt], afn[mt][0], afn[mt][1], afn[mt][2], afn[mt][3],
                        (nt & 1) ? b[2] : b[0], (nt & 1) ? b[3] : b[1]);
            }
    }

    // ---- epilogue ----
    #pragma unroll
    for (int mt = 0; mt < 4; mt++) {
        const int r0 = blockIdx.y * TILE_M + warpM * 64 + mt * 16 + lq;
        #pragma unroll
        for (int nt = 0; nt < 4; nt++) {
            const int c0 = blockIdx.x * TILE_N + warpN * 32 + nt * 8 + 2 * lr;
            float v0 = acc[mt][nt][0], v1 = acc[mt][nt][1];
            float v2 = acc[mt][nt][2], v3 = acc[mt][nt][3];
            if (RELU) {
                v0 = fmaxf(v0, 0.0f); v1 = fmaxf(v1, 0.0f);
                v2 = fmaxf(v2, 0.0f); v3 = fmaxf(v3, 0.0f);
            }
            if (OUT_HALF) {
                __half* C = (__half*)Cv + e * SC;
                *reinterpret_cast<__half2*>(C + (long long)r0 * LDC + c0)       = __floats2half2_rn(v0, v1);
                *reinterpret_cast<__half2*>(C + (long long)(r0 + 8) * LDC + c0) = __floats2half2_rn(v2, v3);
            } else {
                float* C = (float*)Cv + e * SC;
                *reinterpret_cast<float2*>(C + (long long)r0 * LDC + c0)       = make_float2(v0, v1);
                *reinterpret_cast<float2*>(C + (long long)(r0 + 8) * LDC + c0) = make_float2(v2, v3);
            }
        }
    }
}

// ---------------- launch ----------------
extern "C" void kernel_launch(void* const* d_in, const int* in_sizes, int n_in,
                              void* d_out, int out_size)
{
    const float* X  = (const float*)d_in[0];
    const float* W1 = (const float*)d_in[2];
    const float* W2 = (const float*)d_in[3];
    float* Y = (float*)d_out;

    __half *Xh, *W1h, *W2h, *Hh;
    cudaGetSymbolAddress((void**)&Xh,  g_Xh);
    cudaGetSymbolAddress((void**)&W1h, g_W1h);
    cudaGetSymbolAddress((void**)&W2h, g_W2h);
    cudaGetSymbolAddress((void**)&Hh,  g_Hh);

    // GEMM1: K=ND, LDA=ND, LDB=NF, LDC=NF; GEMM2: K=NF, LDA=NF, LDB=ND, LDC=ND
    auto* k1 = gemm_f16_mma<true,  true,  ND, ND, NF, NF>;
    auto* k2 = gemm_f16_mma<false, false, NF, NF, ND, ND>;

    static bool attr_set = false;
    if (!attr_set) {
        cudaFuncSetAttribute(k1, cudaFuncAttributeMaxDynamicSharedMemorySize, SM_TOTAL);
        cudaFuncSetAttribute(k2, cudaFuncAttributeMaxDynamicSharedMemorySize, SM_TOTAL);
        attr_set = true;
    }

    // casts
    {
        size_t n4 = (size_t)NE * NC * ND / 4;
        f32_to_f16_kernel<<<(unsigned)((n4 + 255) / 256), 256>>>(X, Xh, n4);
    }
    {
        size_t n4 = (size_t)NE * ND * NF / 4;
        f32_to_f16_kernel<<<(unsigned)((n4 + 255) / 256), 256>>>(W1, W1h, n4);
    }
    {
        size_t n4 = (size_t)NE * NF * ND / 4;
        f32_to_f16_kernel<<<(unsigned)((n4 + 255) / 256), 256>>>(W2, W2h, n4);
    }

    // GEMM1: H = relu(Xh @ W1h)
    {
        dim3 g(NF / TILE_N, NC / TILE_M, NE);
        k1<<<g, 256, SM_TOTAL>>>(Xh, W1h, Hh);
    }
    // GEMM2: Y = H @ W2h
    {
        dim3 g(ND / TILE_N, NC / TILE_M, NE);
        k2<<<g, 256, SM_TOTAL>>>(Hh, W2h, Y);
    }
}

// round 9
// speedup vs baseline: 1.2687x; 1.0006x over previous
#include <cuda_runtime.h>
#include <cuda_fp16.h>
#include <cstdint>
#include <cstddef>

#define NE 8
#define NC 4096
#define ND 1024
#define NF 4096

// Device scratch (no allocs allowed)
__device__ __half g_Xh [(size_t)NE * NC * ND];   // X fp16
__device__ __half g_W1h[(size_t)NE * ND * NF];   // W1 fp16 (natural [D,F])
__device__ __half g_W2h[(size_t)NE * NF * ND];   // W2 fp16 (natural [F,D])
__device__ __half g_Hh [(size_t)NE * NC * NF];   // relu(X@W1) fp16

// ---------------- helpers ----------------
__device__ __forceinline__ uint32_t smem_u32(const void* p) {
    uint32_t a;
    asm("{ .reg .u64 t; cvta.to.shared.u64 t, %1; cvt.u32.u64 %0, t; }" : "=r"(a) : "l"(p));
    return a;
}
__device__ __forceinline__ void cp_async16(uint32_t dst, const void* src) {
    asm volatile("cp.async.cg.shared.global [%0], [%1], 16;" :: "r"(dst), "l"(src));
}
#define CP_COMMIT() asm volatile("cp.async.commit_group;" ::: "memory")
#define CP_WAIT2()  asm volatile("cp.async.wait_group 2;" ::: "memory")

__device__ __forceinline__ void ldmx4(uint32_t r[4], uint32_t addr) {
    asm volatile("ldmatrix.sync.aligned.m8n8.x4.shared.b16 {%0,%1,%2,%3}, [%4];"
        : "=r"(r[0]), "=r"(r[1]), "=r"(r[2]), "=r"(r[3]) : "r"(addr));
}
__device__ __forceinline__ void ldmx4t(uint32_t r[4], uint32_t addr) {
    asm volatile("ldmatrix.sync.aligned.m8n8.x4.trans.shared.b16 {%0,%1,%2,%3}, [%4];"
        : "=r"(r[0]), "=r"(r[1]), "=r"(r[2]), "=r"(r[3]) : "r"(addr));
}
__device__ __forceinline__ void mma_f16(float d[4],
                                        uint32_t a0, uint32_t a1, uint32_t a2, uint32_t a3,
                                        uint32_t b0, uint32_t b1) {
    asm volatile("mma.sync.aligned.m16n8k16.row.col.f32.f16.f16.f32 "
        "{%0,%1,%2,%3}, {%4,%5,%6,%7}, {%8,%9}, {%0,%1,%2,%3};"
        : "+f"(d[0]), "+f"(d[1]), "+f"(d[2]), "+f"(d[3])
        : "r"(a0), "r"(a1), "r"(a2), "r"(a3), "r"(b0), "r"(b1));
}

// ---------------- prep: f32 -> f16 cast ----------------
__global__ void f32_to_f16_kernel(const float* __restrict__ in, __half* __restrict__ out, size_t n4) {
    size_t i = (size_t)blockIdx.x * blockDim.x + threadIdx.x;
    if (i >= n4) return;
    float4 v = reinterpret_cast<const float4*>(in)[i];
    __half2 h0 = __floats2half2_rn(v.x, v.y);
    __half2 h1 = __floats2half2_rn(v.z, v.w);
    uint2 o;
    o.x = *reinterpret_cast<uint32_t*>(&h0);
    o.y = *reinterpret_cast<uint32_t*>(&h1);
    reinterpret_cast<uint2*>(out)[i] = o;
}

// ---------------- fp16 mma.sync GEMM (R6 structure + constexpr strides) ----
// C[M,N] = A[M,K] (K-major) * B[K,N] (N-major), batched over blockIdx.z.
// CTA 128x128, BK=32, 4-stage cp.async, 2 CTAs/SM, fragment double-buffering.
// 8 warps: warpM = wid&1, warpN = wid>>1; warp tile 64x32.
// Mainloop is FORCIBLY not unrolled (unroll 1): a constexpr trip count
// otherwise makes nvcc unroll ~66KB of loop body and thrash the I-cache (R8).
#define STAGES 4
#define BK 32
#define TILE_M 128
#define TILE_N 128
#define AROWB 80                     // A smem: 64B data + 16 pad per row (128 rows)
#define BROWB 272                    // B smem: 256B data + 16 pad per k-row (32 rows)
#define STG_A (TILE_M * AROWB)       // 10240 B
#define STG_B (BK * BROWB)           // 8704 B
#define SM_TOTAL (STAGES * (STG_A + STG_B))   // 75776 B -> 2 CTAs/SM

template<bool RELU, bool OUT_HALF, int K, int LDA, int LDB, int LDC>
__global__ __launch_bounds__(256, 2)
void gemm_f16_mma(const __half* __restrict__ A, const __half* __restrict__ B,
                  void* __restrict__ Cv)
{
    constexpr long long SA = (long long)NC * LDA;
    constexpr long long SB = (long long)K * LDB;
    constexpr long long SC = (long long)NC * LDC;
    constexpr int NITERS = K / BK;

    extern __shared__ char smem[];
    const uint32_t a_base = smem_u32(smem);
    const uint32_t b_base = a_base + STAGES * STG_A;

    const int tid = threadIdx.x;
    const int wid = tid >> 5;
    const int lane = tid & 31;
    const int lq = lane >> 2;
    const int lr = lane & 3;
    const int warpM = wid & 1;
    const int warpN = wid >> 1;

    const long long e = blockIdx.z;
    const __half* Ag = A + e * SA + (long long)blockIdx.y * TILE_M * LDA;
    const __half* Bg = B + e * SB + (long long)blockIdx.x * TILE_N;   // B: [K,N]

    // cp.async slots (512 chunks of 16B per matrix per stage; 2 per thread each)
    uint32_t a_dst[2], b_dst[2], a_off[2], b_off[2];
    #pragma unroll
    for (int j = 0; j < 2; j++) {
        int g = tid + 256 * j;
        int ar = g >> 2, as = g & 3;
        a_dst[j] = ar * AROWB + as * 16;
        a_off[j] = (uint32_t)(ar * LDA + as * 8);
        int br = g >> 4, bc = g & 15;
        b_dst[j] = br * BROWB + bc * 16;
        b_off[j] = (uint32_t)(br * LDB + bc * 8);
    }

    // ldmatrix source offsets (strides ≡16 mod 128 -> conflict-free)
    const uint32_t a_lm = (uint32_t)(warpM * 64 + (lane & 15)) * AROWB + ((lane >> 4) & 1) * 16;
    const uint32_t b_lm = (uint32_t)(lane & 15) * BROWB
                        + (uint32_t)(warpN * 32 + ((lane >> 4) & 1) * 8) * 2;

    // prologue: stages 0..2
    #pragma unroll
    for (int s = 0; s < STAGES - 1; s++) {
        const uint32_t ao = a_base + s * STG_A;
        const uint32_t bo = b_base + s * STG_B;
        const uint32_t ka = (uint32_t)(s * BK);
        const uint32_t kb = ka * (uint32_t)LDB;
        #pragma unroll
        for (int j = 0; j < 2; j++) cp_async16(ao + a_dst[j], Ag + a_off[j] + ka);
        #pragma unroll
        for (int j = 0; j < 2; j++) cp_async16(bo + b_dst[j], Bg + b_off[j] + kb);
        CP_COMMIT();
    }

    float acc[4][4][4];
    #pragma unroll
    for (int i = 0; i < 4; i++)
        #pragma unroll
        for (int j = 0; j < 4; j++)
            #pragma unroll
            for (int k = 0; k < 4; k++)
                acc[i][j][k] = 0.0f;

    uint32_t afc[4][4], bfc[2][4];   // kk=0 frags
    uint32_t afn[4][4], bfn[2][4];   // kk=1 frags

    // wait stage 0, load kk=0 frags
    CP_WAIT2();
    __syncthreads();
    #pragma unroll
    for (int mt = 0; mt < 4; mt++) ldmx4(afc[mt], a_base + a_lm + mt * (16 * AROWB));
    #pragma unroll
    for (int np = 0; np < 2; np++) ldmx4t(bfc[np], b_base + b_lm + np * 32);

    int pre = STAGES - 1;

    #pragma unroll 1
    for (int it = 0; it < NITERS; it++) {
        const int buf = it & (STAGES - 1);
        const uint32_t As = a_base + buf * STG_A;
        const uint32_t Bs = b_base + buf * STG_B;

        // ---- phase kk=0: load kk=1 frags, prefetch gmem, MMA on cur ----
        #pragma unroll
        for (int mt = 0; mt < 4; mt++) ldmx4(afn[mt], As + a_lm + mt * (16 * AROWB) + 32);
        #pragma unroll
        for (int np = 0; np < 2; np++) ldmx4t(bfn[np], Bs + b_lm + 16 * BROWB + np * 32);

        if (pre < NITERS) {
            const int lb = pre & (STAGES - 1);
            const uint32_t ao = a_base + lb * STG_A;
            const uint32_t bo = b_base + lb * STG_B;
            const uint32_t ka = (uint32_t)(pre * BK);
            const uint32_t kb = ka * (uint32_t)LDB;
            #pragma unroll
            for (int j = 0; j < 2; j++) cp_async16(ao + a_dst[j], Ag + a_off[j] + ka);
            #pragma unroll
            for (int j = 0; j < 2; j++) cp_async16(bo + b_dst[j], Bg + b_off[j] + kb);
        }
        CP_COMMIT();
        pre++;

        #pragma unroll
        for (int mt = 0; mt < 4; mt++)
            #pragma unroll
            for (int nt = 0; nt < 4; nt++) {
                const uint32_t* b = bfc[nt >> 1];
                mma_f16(acc[mt][nt], afc[mt][0], afc[mt][1], afc[mt][2], afc[mt][3],
                        (nt & 1) ? b[2] : b[0], (nt & 1) ? b[3] : b[1]);
            }

        // ---- phase kk=1: advance smem stage, load next kk=0 frags, MMA on nxt ----
        if (it + 1 < NITERS) {
            CP_WAIT2();          // stage it+1 landed
            __syncthreads();     // all reads of the slot the next prefetch overwrites are done
            const int nb = (it + 1) & (STAGES - 1);
            const uint32_t As2 = a_base + nb * STG_A;
            const uint32_t Bs2 = b_base + nb * STG_B;
            #pragma unroll
            for (int mt = 0; mt < 4; mt++) ldmx4(afc[mt], As2 + a_lm + mt * (16 * AROWB));
            #pragma unroll
            for (int np = 0; np < 2; np++) ldmx4t(bfc[np], Bs2 + b_lm + np * 32);
        }

        #pragma unroll
        for (int mt = 0; mt < 4; mt++)
            #pragma unroll
            for (int nt = 0; nt < 4; nt++) {
                const uint32_t* b = bfn[nt >> 1];
                mma_f16(acc[mt][nt], afn[mt][0], afn[mt][1], afn[mt][2], afn[mt][3],
                        (nt & 1) ? b[2] : b[0], (nt & 1) ? b[3] : b[1]);
            }
    }

    // ---- epilogue ----
    #pragma unroll
    for (int mt = 0; mt < 4; mt++) {
        const int r0 = blockIdx.y * TILE_M + warpM * 64 + mt * 16 + lq;
        #pragma unroll
        for (int nt = 0; nt < 4; nt++) {
            const int c0 = blockIdx.x * TILE_N + warpN * 32 + nt * 8 + 2 * lr;
            float v0 = acc[mt][nt][0], v1 = acc[mt][nt][1];
            float v2 = acc[mt][nt][2], v3 = acc[mt][nt][3];
            if (RELU) {
                v0 = fmaxf(v0, 0.0f); v1 = fmaxf(v1, 0.0f);
                v2 = fmaxf(v2, 0.0f); v3 = fmaxf(v3, 0.0f);
            }
            if (OUT_HALF) {
                __half* C = (__half*)Cv + e * SC;
                *reinterpret_cast<__half2*>(C + (long long)r0 * LDC + c0)       = __floats2half2_rn(v0, v1);
                *reinterpret_cast<__half2*>(C + (long long)(r0 + 8) * LDC + c0) = __floats2half2_rn(v2, v3);
            } else {
                float* C = (float*)Cv + e * SC;
                *reinterpret_cast<float2*>(C + (long long)r0 * LDC + c0)       = make_float2(v0, v1);
                *reinterpret_cast<float2*>(C + (long long)(r0 + 8) * LDC + c0) = make_float2(v2, v3);
            }
        }
    }
}

// ---------------- launch ----------------
extern "C" void kernel_launch(void* const* d_in, const int* in_sizes, int n_in,
                              void* d_out, int out_size)
{
    const float* X  = (const float*)d_in[0];
    const float* W1 = (const float*)d_in[2];
    const float* W2 = (const float*)d_in[3];
    float* Y = (float*)d_out;

    __half *Xh, *W1h, *W2h, *Hh;
    cudaGetSymbolAddress((void**)&Xh,  g_Xh);
    cudaGetSymbolAddress((void**)&W1h, g_W1h);
    cudaGetSymbolAddress((void**)&W2h, g_W2h);
    cudaGetSymbolAddress((void**)&Hh,  g_Hh);

    // GEMM1: K=ND, LDA=ND, LDB=NF, LDC=NF; GEMM2: K=NF, LDA=NF, LDB=ND, LDC=ND
    auto* k1 = gemm_f16_mma<true,  true,  ND, ND, NF, NF>;
    auto* k2 = gemm_f16_mma<false, false, NF, NF, ND, ND>;

    static bool attr_set = false;
    if (!attr_set) {
        cudaFuncSetAttribute(k1, cudaFuncAttributeMaxDynamicSharedMemorySize, SM_TOTAL);
        cudaFuncSetAttribute(k2, cudaFuncAttributeMaxDynamicSharedMemorySize, SM_TOTAL);
        attr_set = true;
    }

    // casts
    {
        size_t n4 = (size_t)NE * NC * ND / 4;
        f32_to_f16_kernel<<<(unsigned)((n4 + 255) / 256), 256>>>(X, Xh, n4);
    }
    {
        size_t n4 = (size_t)NE * ND * NF / 4;
        f32_to_f16_kernel<<<(unsigned)((n4 + 255) / 256), 256>>>(W1, W1h, n4);
    }
    {
        size_t n4 = (size_t)NE * NF * ND / 4;
        f32_to_f16_kernel<<<(unsigned)((n4 + 255) / 256), 256>>>(W2, W2h, n4);
    }

    // GEMM1: H = relu(Xh @ W1h)
    {
        dim3 g(NF / TILE_N, NC / TILE_M, NE);
        k1<<<g, 256, SM_TOTAL>>>(Xh, W1h, Hh);
    }
    // GEMM2: Y = H @ W2h
    {
        dim3 g(ND / TILE_N, NC / TILE_M, NE);
        k2<<<g, 256, SM_TOTAL>>>(Hh, W2h, Y);
    }
}

// round 10
// speedup vs baseline: 1.4862x; 1.1714x over previous
#include <cuda_runtime.h>
#include <cuda_fp16.h>
#include <cstdint>
#include <cstddef>

#define NE 8
#define NC 4096
#define ND 1024
#define NF 4096

// Device scratch (no allocs allowed)
__device__ __half g_Xh [(size_t)NE * NC * ND];   // X fp16
__device__ __half g_W1h[(size_t)NE * ND * NF];   // W1 fp16 (natural [D,F])
__device__ __half g_W2h[(size_t)NE * NF * ND];   // W2 fp16 (natural [F,D])
__device__ __half g_Hh [(size_t)NE * NC * NF];   // relu(X@W1) fp16

// ---------------- helpers ----------------
__device__ __forceinline__ uint32_t smem_u32(const void* p) {
    uint32_t a;
    asm("{ .reg .u64 t; cvta.to.shared.u64 t, %1; cvt.u32.u64 %0, t; }" : "=r"(a) : "l"(p));
    return a;
}
__device__ __forceinline__ void cp_async16(uint32_t dst, const void* src) {
    asm volatile("cp.async.cg.shared.global [%0], [%1], 16;" :: "r"(dst), "l"(src));
}
#define CP_COMMIT() asm volatile("cp.async.commit_group;" ::: "memory")
#define CP_WAIT3()  asm volatile("cp.async.wait_group 3;" ::: "memory")

__device__ __forceinline__ void ldmx4(uint32_t r[4], uint32_t addr) {
    asm volatile("ldmatrix.sync.aligned.m8n8.x4.shared.b16 {%0,%1,%2,%3}, [%4];"
        : "=r"(r[0]), "=r"(r[1]), "=r"(r[2]), "=r"(r[3]) : "r"(addr));
}
__device__ __forceinline__ void ldmx4t(uint32_t r[4], uint32_t addr) {
    asm volatile("ldmatrix.sync.aligned.m8n8.x4.trans.shared.b16 {%0,%1,%2,%3}, [%4];"
        : "=r"(r[0]), "=r"(r[1]), "=r"(r[2]), "=r"(r[3]) : "r"(addr));
}
__device__ __forceinline__ void mma_f16(float d[4],
                                        uint32_t a0, uint32_t a1, uint32_t a2, uint32_t a3,
                                        uint32_t b0, uint32_t b1) {
    asm volatile("mma.sync.aligned.m16n8k16.row.col.f32.f16.f16.f32 "
        "{%0,%1,%2,%3}, {%4,%5,%6,%7}, {%8,%9}, {%0,%1,%2,%3};"
        : "+f"(d[0]), "+f"(d[1]), "+f"(d[2]), "+f"(d[3])
        : "r"(a0), "r"(a1), "r"(a2), "r"(a3), "r"(b0), "r"(b1));
}

// ---------------- prep: f32 -> f16 cast ----------------
__global__ void f32_to_f16_kernel(const float* __restrict__ in, __half* __restrict__ out, size_t n4) {
    size_t i = (size_t)blockIdx.x * blockDim.x + threadIdx.x;
    if (i >= n4) return;
    float4 v = reinterpret_cast<const float4*>(in)[i];
    __half2 h0 = __floats2half2_rn(v.x, v.y);
    __half2 h1 = __floats2half2_rn(v.z, v.w);
    uint2 o;
    o.x = *reinterpret_cast<uint32_t*>(&h0);
    o.y = *reinterpret_cast<uint32_t*>(&h1);
    reinterpret_cast<uint2*>(out)[i] = o;
}

// ---------------- fp16 mma.sync GEMM (R6 structure, 5-stage pipeline) ------
// C[M,N] = A[M,K] (K-major) * B[K,N] (N-major), batched over blockIdx.z.
// CTA 128x128, BK=32, 5-stage cp.async (lead 3 iters > DRAM latency),
// 2 CTAs/SM, fragment double-buffering. 8 warps; warp tile 64x32.
// NOTE: runtime dims on purpose — the constexpr-dim variant (R8/R9) made
// ptxas schedule the mainloop ~15% worse at the 128-reg ceiling.
#define STAGES 5
#define BK 32
#define TILE_M 128
#define TILE_N 128
#define AROWB 80                     // A smem: 64B data + 16 pad per row (128 rows)
#define BROWB 272                    // B smem: 256B data + 16 pad per k-row (32 rows)
#define STG_A (TILE_M * AROWB)       // 10240 B
#define STG_B (BK * BROWB)           // 8704 B
#define SM_TOTAL (STAGES * (STG_A + STG_B))   // 94720 B -> 2 CTAs/SM (189.4 KB)

template<bool RELU, bool OUT_HALF>
__global__ __launch_bounds__(256, 2)
void gemm_f16_mma(const __half* __restrict__ A, const __half* __restrict__ B,
                  void* __restrict__ Cv,
                  int K, int lda, int ldb, int ldc,
                  long long sA, long long sB, long long sC)
{
    extern __shared__ char smem[];
    const uint32_t a_base = smem_u32(smem);
    const uint32_t b_base = a_base + STAGES * STG_A;

    const int tid = threadIdx.x;
    const int wid = tid >> 5;
    const int lane = tid & 31;
    const int lq = lane >> 2;
    const int lr = lane & 3;
    const int warpM = wid & 1;
    const int warpN = wid >> 1;

    const long long e = blockIdx.z;
    const __half* Ag = A + e * sA + (long long)blockIdx.y * TILE_M * lda;
    const __half* Bg = B + e * sB + (long long)blockIdx.x * TILE_N;   // B: [K,N]

    // cp.async slots (512 chunks of 16B per matrix per stage; 2 per thread each)
    uint32_t a_dst[2], b_dst[2], a_off[2], b_off[2];
    #pragma unroll
    for (int j = 0; j < 2; j++) {
        int g = tid + 256 * j;
        int ar = g >> 2, as = g & 3;
        a_dst[j] = ar * AROWB + as * 16;
        a_off[j] = (uint32_t)(ar * lda + as * 8);
        int br = g >> 4, bc = g & 15;
        b_dst[j] = br * BROWB + bc * 16;
        b_off[j] = (uint32_t)(br * ldb + bc * 8);
    }

    // ldmatrix source offsets (strides ≡16 mod 128 -> conflict-free)
    const uint32_t a_lm = (uint32_t)(warpM * 64 + (lane & 15)) * AROWB + ((lane >> 4) & 1) * 16;
    const uint32_t b_lm = (uint32_t)(lane & 15) * BROWB
                        + (uint32_t)(warpN * 32 + ((lane >> 4) & 1) * 8) * 2;

    const int niters = K / BK;

    // prologue: stages 0..3
    #pragma unroll
    for (int s = 0; s < STAGES - 1; s++) {
        const uint32_t ao = a_base + s * STG_A;
        const uint32_t bo = b_base + s * STG_B;
        const uint32_t ka = (uint32_t)(s * BK);
        const uint32_t kb = ka * (uint32_t)ldb;
        #pragma unroll
        for (int j = 0; j < 2; j++) cp_async16(ao + a_dst[j], Ag + a_off[j] + ka);
        #pragma unroll
        for (int j = 0; j < 2; j++) cp_async16(bo + b_dst[j], Bg + b_off[j] + kb);
        CP_COMMIT();
    }

    float acc[4][4][4];
    #pragma unroll
    for (int i = 0; i < 4; i++)
        #pragma unroll
        for (int j = 0; j < 4; j++)
            #pragma unroll
            for (int k = 0; k < 4; k++)
                acc[i][j][k] = 0.0f;

    uint32_t afc[4][4], bfc[2][4];   // kk=0 frags
    uint32_t afn[4][4], bfn[2][4];   // kk=1 frags

    // wait stage 0 (3 groups may remain outstanding), load kk=0 frags
    CP_WAIT3();
    __syncthreads();
    #pragma unroll
    for (int mt = 0; mt < 4; mt++) ldmx4(afc[mt], a_base + a_lm + mt * (16 * AROWB));
    #pragma unroll
    for (int np = 0; np < 2; np++) ldmx4t(bfc[np], b_base + b_lm + np * 32);

    int pre = STAGES - 1;
    int buf = 0;

    for (int it = 0; it < niters; it++) {
        const uint32_t As = a_base + buf * STG_A;
        const uint32_t Bs = b_base + buf * STG_B;

        // ---- phase kk=0: load kk=1 frags, prefetch gmem, MMA on cur ----
        #pragma unroll
        for (int mt = 0; mt < 4; mt++) ldmx4(afn[mt], As + a_lm + mt * (16 * AROWB) + 32);
        #pragma unroll
        for (int np = 0; np < 2; np++) ldmx4t(bfn[np], Bs + b_lm + 16 * BROWB + np * 32);

        if (pre < niters) {
            int lb = pre - (pre / STAGES) * STAGES;     // pre % 5
            const uint32_t ao = a_base + lb * STG_A;
            const uint32_t bo = b_base + lb * STG_B;
            const uint32_t ka = (uint32_t)(pre * BK);
            const uint32_t kb = ka * (uint32_t)ldb;
            #pragma unroll
            for (int j = 0; j < 2; j++) cp_async16(ao + a_dst[j], Ag + a_off[j] + ka);
            #pragma unroll
            for (int j = 0; j < 2; j++) cp_async16(bo + b_dst[j], Bg + b_off[j] + kb);
        }
        CP_COMMIT();
        pre++;

        #pragma unroll
        for (int mt = 0; mt < 4; mt++)
            #pragma unroll
            for (int nt = 0; nt < 4; nt++) {
                const uint32_t* b = bfc[nt >> 1];
                mma_f16(acc[mt][nt], afc[mt][0], afc[mt][1], afc[mt][2], afc[mt][3],
                        (nt & 1) ? b[2] : b[0], (nt & 1) ? b[3] : b[1]);
            }

        // ---- phase kk=1: advance smem stage, load next kk=0 frags, MMA on nxt ----
        if (it + 1 < niters) {
            CP_WAIT3();          // stage it+1 landed (<=3 groups in flight)
            __syncthreads();     // all reads of the slot the next prefetch overwrites are issued
            int nb = buf + 1; if (nb == STAGES) nb = 0;
            const uint32_t As2 = a_base + nb * STG_A;
            const uint32_t Bs2 = b_base + nb * STG_B;
            #pragma unroll
            for (int mt = 0; mt < 4; mt++) ldmx4(afc[mt], As2 + a_lm + mt * (16 * AROWB));
            #pragma unroll
            for (int np = 0; np < 2; np++) ldmx4t(bfc[np], Bs2 + b_lm + np * 32);
            buf = nb;
        }

        #pragma unroll
        for (int mt = 0; mt < 4; mt++)
            #pragma unroll
            for (int nt = 0; nt < 4; nt++) {
                const uint32_t* b = bfn[nt >> 1];
                mma_f16(acc[mt][nt], afn[mt][0], afn[mt][1], afn[mt][2], afn[mt][3],
                        (nt & 1) ? b[2] : b[0], (nt & 1) ? b[3] : b[1]);
            }
    }

    // ---- epilogue ----
    #pragma unroll
    for (int mt = 0; mt < 4; mt++) {
        const int r0 = blockIdx.y * TILE_M + warpM * 64 + mt * 16 + lq;
        #pragma unroll
        for (int nt = 0; nt < 4; nt++) {
            const int c0 = blockIdx.x * TILE_N + warpN * 32 + nt * 8 + 2 * lr;
            float v0 = acc[mt][nt][0], v1 = acc[mt][nt][1];
            float v2 = acc[mt][nt][2], v3 = acc[mt][nt][3];
            if (RELU) {
                v0 = fmaxf(v0, 0.0f); v1 = fmaxf(v1, 0.0f);
                v2 = fmaxf(v2, 0.0f); v3 = fmaxf(v3, 0.0f);
            }
            if (OUT_HALF) {
                __half* C = (__half*)Cv + e * sC;
                *reinterpret_cast<__half2*>(C + (long long)r0 * ldc + c0)       = __floats2half2_rn(v0, v1);
                *reinterpret_cast<__half2*>(C + (long long)(r0 + 8) * ldc + c0) = __floats2half2_rn(v2, v3);
            } else {
                float* C = (float*)Cv + e * sC;
                *reinterpret_cast<float2*>(C + (long long)r0 * ldc + c0)       = make_float2(v0, v1);
                *reinterpret_cast<float2*>(C + (long long)(r0 + 8) * ldc + c0) = make_float2(v2, v3);
            }
        }
    }
}

// ---------------- launch ----------------
extern "C" void kernel_launch(void* const* d_in, const int* in_sizes, int n_in,
                              void* d_out, int out_size)
{
    const float* X  = (const float*)d_in[0];
    const float* W1 = (const float*)d_in[2];
    const float* W2 = (const float*)d_in[3];
    float* Y = (float*)d_out;

    __half *Xh, *W1h, *W2h, *Hh;
    cudaGetSymbolAddress((void**)&Xh,  g_Xh);
    cudaGetSymbolAddress((void**)&W1h, g_W1h);
    cudaGetSymbolAddress((void**)&W2h, g_W2h);
    cudaGetSymbolAddress((void**)&Hh,  g_Hh);

    static bool attr_set = false;
    if (!attr_set) {
        cudaFuncSetAttribute(gemm_f16_mma<true, true>,   cudaFuncAttributeMaxDynamicSharedMemorySize, SM_TOTAL);
        cudaFuncSetAttribute(gemm_f16_mma<false, false>, cudaFuncAttributeMaxDynamicSharedMemorySize, SM_TOTAL);
        attr_set = true;
    }

    // casts
    {
        size_t n4 = (size_t)NE * NC * ND / 4;
        f32_to_f16_kernel<<<(unsigned)((n4 + 255) / 256), 256>>>(X, Xh, n4);
    }
    {
        size_t n4 = (size_t)NE * ND * NF / 4;
        f32_to_f16_kernel<<<(unsigned)((n4 + 255) / 256), 256>>>(W1, W1h, n4);
    }
    {
        size_t n4 = (size_t)NE * NF * ND / 4;
        f32_to_f16_kernel<<<(unsigned)((n4 + 255) / 256), 256>>>(W2, W2h, n4);
    }

    // GEMM1: H = relu(Xh @ W1h); M=C, N=F, K=D; ldb=NF
    {
        dim3 g(NF / TILE_N, NC / TILE_M, NE);
        gemm_f16_mma<true, true><<<g, 256, SM_TOTAL>>>(
            Xh, W1h, Hh,
            ND, ND, NF, NF,
            (long long)NC * ND, (long long)ND * NF, (long long)NC * NF);
    }
    // GEMM2: Y = H @ W2h; M=C, N=D, K=F; ldb=ND
    {
        dim3 g(ND / TILE_N, NC / TILE_M, NE);
        gemm_f16_mma<false, false><<<g, 256, SM_TOTAL>>>(
            Hh, W2h, Y,
            NF, NF, ND, ND,
            (long long)NC * NF, (long long)NF * ND, (long long)NC * ND);
    }
}

// round 11
// speedup vs baseline: 1.5551x; 1.0464x over previous
#include <cuda_runtime.h>
#include <cuda_fp16.h>
#include <cstdint>
#include <cstddef>

#define NE 8
#define NC 4096
#define ND 1024
#define NF 4096

// Device scratch (no allocs allowed)
__device__ __half g_Xh [(size_t)NE * NC * ND];   // X fp16
__device__ __half g_W1h[(size_t)NE * ND * NF];   // W1 fp16 (natural [D,F])
__device__ __half g_W2h[(size_t)NE * NF * ND];   // W2 fp16 (natural [F,D])
__device__ __half g_Hh [(size_t)NE * NC * NF];   // relu(X@W1) fp16

// ---------------- helpers ----------------
__device__ __forceinline__ uint32_t smem_u32(const void* p) {
    uint32_t a;
    asm("{ .reg .u64 t; cvta.to.shared.u64 t, %1; cvt.u32.u64 %0, t; }" : "=r"(a) : "l"(p));
    return a;
}
__device__ __forceinline__ void cp_async16(uint32_t dst, const void* src) {
    asm volatile("cp.async.cg.shared.global [%0], [%1], 16;" :: "r"(dst), "l"(src));
}
#define CP_COMMIT() asm volatile("cp.async.commit_group;" ::: "memory")
#define CP_WAIT2()  asm volatile("cp.async.wait_group 2;" ::: "memory")

__device__ __forceinline__ void ldmx4(uint32_t r[4], uint32_t addr) {
    asm volatile("ldmatrix.sync.aligned.m8n8.x4.shared.b16 {%0,%1,%2,%3}, [%4];"
        : "=r"(r[0]), "=r"(r[1]), "=r"(r[2]), "=r"(r[3]) : "r"(addr));
}
__device__ __forceinline__ void ldmx4t(uint32_t r[4], uint32_t addr) {
    asm volatile("ldmatrix.sync.aligned.m8n8.x4.trans.shared.b16 {%0,%1,%2,%3}, [%4];"
        : "=r"(r[0]), "=r"(r[1]), "=r"(r[2]), "=r"(r[3]) : "r"(addr));
}
__device__ __forceinline__ void mma_f16(float d[4],
                                        uint32_t a0, uint32_t a1, uint32_t a2, uint32_t a3,
                                        uint32_t b0, uint32_t b1) {
    asm volatile("mma.sync.aligned.m16n8k16.row.col.f32.f16.f16.f32 "
        "{%0,%1,%2,%3}, {%4,%5,%6,%7}, {%8,%9}, {%0,%1,%2,%3};"
        : "+f"(d[0]), "+f"(d[1]), "+f"(d[2]), "+f"(d[3])
        : "r"(a0), "r"(a1), "r"(a2), "r"(a3), "r"(b0), "r"(b1));
}

// ---------------- prep: f32 -> f16 cast ----------------
__global__ void f32_to_f16_kernel(const float* __restrict__ in, __half* __restrict__ out, size_t n4) {
    size_t i = (size_t)blockIdx.x * blockDim.x + threadIdx.x;
    if (i >= n4) return;
    float4 v = reinterpret_cast<const float4*>(in)[i];
    __half2 h0 = __floats2half2_rn(v.x, v.y);
    __half2 h1 = __floats2half2_rn(v.z, v.w);
    uint2 o;
    o.x = *reinterpret_cast<uint32_t*>(&h0);
    o.y = *reinterpret_cast<uint32_t*>(&h1);
    reinterpret_cast<uint2*>(out)[i] = o;
}

// ---------------- fp16 mma.sync GEMM: 128 threads, warp tile 64x64 ---------
// C[M,N] = A[M,K] (K-major) * B[K,N] (N-major), batched over blockIdx.z.
// CTA 128x128, BK=32, 4-stage cp.async, 2 CTAs/SM (128 thr, <=256 regs).
// 4 warps in 2x2: warpM = wid&1, warpN = wid>>1; warp tile 64x64.
// Halves smem fragment amplification vs the 8-warp 64x32 layout (R6).
#define STAGES 4
#define BK 32
#define TILE_M 128
#define TILE_N 128
#define NTHREADS 128
#define AROWB 80                     // A smem: 64B data + 16 pad per row (128 rows)
#define BROWB 272                    // B smem: 256B data + 16 pad per k-row (32 rows)
#define STG_A (TILE_M * AROWB)       // 10240 B
#define STG_B (BK * BROWB)           // 8704 B
#define SM_TOTAL (STAGES * (STG_A + STG_B))   // 75776 B -> 2 CTAs/SM

template<bool RELU, bool OUT_HALF>
__global__ __launch_bounds__(NTHREADS, 2)
void gemm_f16_mma(const __half* __restrict__ A, const __half* __restrict__ B,
                  void* __restrict__ Cv,
                  int K, int lda, int ldb, int ldc,
                  long long sA, long long sB, long long sC)
{
    extern __shared__ char smem[];
    const uint32_t a_base = smem_u32(smem);
    const uint32_t b_base = a_base + STAGES * STG_A;

    const int tid = threadIdx.x;
    const int wid = tid >> 5;
    const int lane = tid & 31;
    const int lq = lane >> 2;
    const int lr = lane & 3;
    const int warpM = wid & 1;     // 0..1 (64 rows each)
    const int warpN = wid >> 1;    // 0..1 (64 cols each)

    const long long e = blockIdx.z;
    const __half* Ag = A + e * sA + (long long)blockIdx.y * TILE_M * lda;
    const __half* Bg = B + e * sB + (long long)blockIdx.x * TILE_N;   // B: [K,N]

    // cp.async slots: 512 chunks of 16B per matrix per stage; 4 per thread each.
    uint32_t a_dst[4], b_dst[4], a_off[4], b_off[4];
    #pragma unroll
    for (int j = 0; j < 4; j++) {
        int g = tid + NTHREADS * j;
        int ar = g >> 2, as = g & 3;               // A: row 0..127, 16B seg 0..3
        a_dst[j] = ar * AROWB + as * 16;
        a_off[j] = (uint32_t)(ar * lda + as * 8);
        int br = g >> 4, bc = g & 15;              // B: k-row 0..31, 16B col 0..15
        b_dst[j] = br * BROWB + bc * 16;
        b_off[j] = (uint32_t)(br * ldb + bc * 8);
    }

    // ldmatrix source offsets (strides ≡16 mod 128 -> conflict-free)
    const uint32_t a_lm = (uint32_t)(warpM * 64 + (lane & 15)) * AROWB + ((lane >> 4) & 1) * 16;
    const uint32_t b_lm = (uint32_t)(lane & 15) * BROWB
                        + (uint32_t)(warpN * 64 + ((lane >> 4) & 1) * 8) * 2;

    const int niters = K / BK;

    // prologue: stages 0..2
    #pragma unroll
    for (int s = 0; s < STAGES - 1; s++) {
        const uint32_t ao = a_base + s * STG_A;
        const uint32_t bo = b_base + s * STG_B;
        const uint32_t ka = (uint32_t)(s * BK);
        const uint32_t kb = ka * (uint32_t)ldb;
        #pragma unroll
        for (int j = 0; j < 4; j++) cp_async16(ao + a_dst[j], Ag + a_off[j] + ka);
        #pragma unroll
        for (int j = 0; j < 4; j++) cp_async16(bo + b_dst[j], Bg + b_off[j] + kb);
        CP_COMMIT();
    }

    float acc[4][8][4];                           // 128 accumulators
    #pragma unroll
    for (int i = 0; i < 4; i++)
        #pragma unroll
        for (int j = 0; j < 8; j++)
            #pragma unroll
            for (int k = 0; k < 4; k++)
                acc[i][j][k] = 0.0f;

    uint32_t afc[4][4], bfc[4][4];   // kk=0 frags (A: 64 rows, B: 64 cols)
    uint32_t afn[4][4], bfn[4][4];   // kk=1 frags

    // wait stage 0, load kk=0 frags
    CP_WAIT2();
    __syncthreads();
    #pragma unroll
    for (int mt = 0; mt < 4; mt++) ldmx4(afc[mt], a_base + a_lm + mt * (16 * AROWB));
    #pragma unroll
    for (int np = 0; np < 4; np++) ldmx4t(bfc[np], b_base + b_lm + np * 32);

    int pre = STAGES - 1;

    for (int it = 0; it < niters; it++) {
        const int buf = it & (STAGES - 1);
        const uint32_t As = a_base + buf * STG_A;
        const uint32_t Bs = b_base + buf * STG_B;

        // ---- phase kk=0: load kk=1 frags, prefetch gmem, MMA on cur ----
        #pragma unroll
        for (int mt = 0; mt < 4; mt++) ldmx4(afn[mt], As + a_lm + mt * (16 * AROWB) + 32);
        #pragma unroll
        for (int np = 0; np < 4; np++) ldmx4t(bfn[np], Bs + b_lm + 16 * BROWB + np * 32);

        if (pre < niters) {
            const int lb = pre & (STAGES - 1);
            const uint32_t ao = a_base + lb * STG_A;
            const uint32_t bo = b_base + lb * STG_B;
            const uint32_t ka = (uint32_t)(pre * BK);
            const uint32_t kb = ka * (uint32_t)ldb;
            #pragma unroll
            for (int j = 0; j < 4; j++) cp_async16(ao + a_dst[j], Ag + a_off[j] + ka);
            #pragma unroll
            for (int j = 0; j < 4; j++) cp_async16(bo + b_dst[j], Bg + b_off[j] + kb);
        }
        CP_COMMIT();
        pre++;

        #pragma unroll
        for (int mt = 0; mt < 4; mt++)
            #pragma unroll
            for (int nt = 0; nt < 8; nt++) {
                const uint32_t* b = bfc[nt >> 1];
                mma_f16(acc[mt][nt], afc[mt][0], afc[mt][1], afc[mt][2], afc[mt][3],
                        (nt & 1) ? b[2] : b[0], (nt & 1) ? b[3] : b[1]);
            }

        // ---- phase kk=1: advance smem stage, load next kk=0 frags, MMA on nxt ----
        if (it + 1 < niters) {
            CP_WAIT2();          // stage it+1 landed
            __syncthreads();     // all reads of the slot the next prefetch overwrites are done
            const int nb = (it + 1) & (STAGES - 1);
            const uint32_t As2 = a_base + nb * STG_A;
            const uint32_t Bs2 = b_base + nb * STG_B;
            #pragma unroll
            for (int mt = 0; mt < 4; mt++) ldmx4(afc[mt], As2 + a_lm + mt * (16 * AROWB));
            #pragma unroll
            for (int np = 0; np < 4; np++) ldmx4t(bfc[np], Bs2 + b_lm + np * 32);
        }

        #pragma unroll
        for (int mt = 0; mt < 4; mt++)
            #pragma unroll
            for (int nt = 0; nt < 8; nt++) {
                const uint32_t* b = bfn[nt >> 1];
                mma_f16(acc[mt][nt], afn[mt][0], afn[mt][1], afn[mt][2], afn[mt][3],
                        (nt & 1) ? b[2] : b[0], (nt & 1) ? b[3] : b[1]);
            }
    }

    // ---- epilogue ----
    #pragma unroll
    for (int mt = 0; mt < 4; mt++) {
        const int r0 = blockIdx.y * TILE_M + warpM * 64 + mt * 16 + lq;
        #pragma unroll
        for (int nt = 0; nt < 8; nt++) {
            const int c0 = blockIdx.x * TILE_N + warpN * 64 + nt * 8 + 2 * lr;
            float v0 = acc[mt][nt][0], v1 = acc[mt][nt][1];
            float v2 = acc[mt][nt][2], v3 = acc[mt][nt][3];
            if (RELU) {
                v0 = fmaxf(v0, 0.0f); v1 = fmaxf(v1, 0.0f);
                v2 = fmaxf(v2, 0.0f); v3 = fmaxf(v3, 0.0f);
            }
            if (OUT_HALF) {
                __half* C = (__half*)Cv + e * sC;
                *reinterpret_cast<__half2*>(C + (long long)r0 * ldc + c0)       = __floats2half2_rn(v0, v1);
                *reinterpret_cast<__half2*>(C + (long long)(r0 + 8) * ldc + c0) = __floats2half2_rn(v2, v3);
            } else {
                float* C = (float*)Cv + e * sC;
                *reinterpret_cast<float2*>(C + (long long)r0 * ldc + c0)       = make_float2(v0, v1);
                *reinterpret_cast<float2*>(C + (long long)(r0 + 8) * ldc + c0) = make_float2(v2, v3);
            }
        }
    }
}

// ---------------- launch ----------------
extern "C" void kernel_launch(void* const* d_in, const int* in_sizes, int n_in,
                              void* d_out, int out_size)
{
    const float* X  = (const float*)d_in[0];
    const float* W1 = (const float*)d_in[2];
    const float* W2 = (const float*)d_in[3];
    float* Y = (float*)d_out;

    __half *Xh, *W1h, *W2h, *Hh;
    cudaGetSymbolAddress((void**)&Xh,  g_Xh);
    cudaGetSymbolAddress((void**)&W1h, g_W1h);
    cudaGetSymbolAddress((void**)&W2h, g_W2h);
    cudaGetSymbolAddress((void**)&Hh,  g_Hh);

    static bool attr_set = false;
    if (!attr_set) {
        cudaFuncSetAttribute(gemm_f16_mma<true, true>,   cudaFuncAttributeMaxDynamicSharedMemorySize, SM_TOTAL);
        cudaFuncSetAttribute(gemm_f16_mma<false, false>, cudaFuncAttributeMaxDynamicSharedMemorySize, SM_TOTAL);
        attr_set = true;
    }

    // casts
    {
        size_t n4 = (size_t)NE * NC * ND / 4;
        f32_to_f16_kernel<<<(unsigned)((n4 + 255) / 256), 256>>>(X, Xh, n4);
    }
    {
        size_t n4 = (size_t)NE * ND * NF / 4;
        f32_to_f16_kernel<<<(unsigned)((n4 + 255) / 256), 256>>>(W1, W1h, n4);
    }
    {
        size_t n4 = (size_t)NE * NF * ND / 4;
        f32_to_f16_kernel<<<(unsigned)((n4 + 255) / 256), 256>>>(W2, W2h, n4);
    }

    // GEMM1: H = relu(Xh @ W1h); M=C, N=F, K=D; ldb=NF
    {
        dim3 g(NF / TILE_N, NC / TILE_M, NE);
        gemm_f16_mma<true, true><<<g, NTHREADS, SM_TOTAL>>>(
            Xh, W1h, Hh,
            ND, ND, NF, NF,
            (long long)NC * ND, (long long)ND * NF, (long long)NC * NF);
    }
    // GEMM2: Y = H @ W2h; M=C, N=D, K=F; ldb=ND
    {
        dim3 g(ND / TILE_N, NC / TILE_M, NE);
        gemm_f16_mma<false, false><<<g, NTHREADS, SM_TOTAL>>>(
            Hh, W2h, Y,
            NF, NF, ND, ND,
            (long long)NC * NF, (long long)NF * ND, (long long)NC * ND);
    }
}

// round 13
// speedup vs baseline: 1.6743x; 1.0766x over previous
#include <cuda_runtime.h>
#include <cuda_fp16.h>
#include <cstdint>
#include <cstddef>

#define NE 8
#define NC 4096
#define ND 1024
#define NF 4096

// Device scratch (no allocs allowed)
__device__ __half g_Xh [(size_t)NE * NC * ND];   // X fp16
__device__ __half g_W1h[(size_t)NE * ND * NF];   // W1 fp16 (natural [D,F])
__device__ __half g_W2h[(size_t)NE * NF * ND];   // W2 fp16 (natural [F,D])
__device__ __half g_Hh [(size_t)NE * NC * NF];   // relu(X@W1) fp16

// ---------------- helpers ----------------
__device__ __forceinline__ uint32_t smem_u32(const void* p) {
    uint32_t a;
    asm("{ .reg .u64 t; cvta.to.shared.u64 t, %1; cvt.u32.u64 %0, t; }" : "=r"(a) : "l"(p));
    return a;
}
__device__ __forceinline__ void cp_async16(uint32_t dst, const void* src) {
    asm volatile("cp.async.cg.shared.global [%0], [%1], 16;" :: "r"(dst), "l"(src));
}
#define CP_COMMIT() asm volatile("cp.async.commit_group;" ::: "memory")
#define CP_WAIT1()  asm volatile("cp.async.wait_group 1;" ::: "memory")

__device__ __forceinline__ void ldmx4(uint32_t r[4], uint32_t addr) {
    asm volatile("ldmatrix.sync.aligned.m8n8.x4.shared.b16 {%0,%1,%2,%3}, [%4];"
        : "=r"(r[0]), "=r"(r[1]), "=r"(r[2]), "=r"(r[3]) : "r"(addr));
}
__device__ __forceinline__ void ldmx4t(uint32_t r[4], uint32_t addr) {
    asm volatile("ldmatrix.sync.aligned.m8n8.x4.trans.shared.b16 {%0,%1,%2,%3}, [%4];"
        : "=r"(r[0]), "=r"(r[1]), "=r"(r[2]), "=r"(r[3]) : "r"(addr));
}
__device__ __forceinline__ void mma_f16(float d[4],
                                        uint32_t a0, uint32_t a1, uint32_t a2, uint32_t a3,
                                        uint32_t b0, uint32_t b1) {
    asm volatile("mma.sync.aligned.m16n8k16.row.col.f32.f16.f16.f32 "
        "{%0,%1,%2,%3}, {%4,%5,%6,%7}, {%8,%9}, {%0,%1,%2,%3};"
        : "+f"(d[0]), "+f"(d[1]), "+f"(d[2]), "+f"(d[3])
        : "r"(a0), "r"(a1), "r"(a2), "r"(a3), "r"(b0), "r"(b1));
}

// ---------------- prep: f32 -> f16 cast ----------------
__global__ void f32_to_f16_kernel(const float* __restrict__ in, __half* __restrict__ out, size_t n4) {
    size_t i = (size_t)blockIdx.x * blockDim.x + threadIdx.x;
    if (i >= n4) return;
    float4 v = reinterpret_cast<const float4*>(in)[i];
    __half2 h0 = __floats2half2_rn(v.x, v.y);
    __half2 h1 = __floats2half2_rn(v.z, v.w);
    uint2 o;
    o.x = *reinterpret_cast<uint32_t*>(&h0);
    o.y = *reinterpret_cast<uint32_t*>(&h1);
    reinterpret_cast<uint2*>(out)[i] = o;
}

// ---------------- fp16 mma.sync GEMM: 128 thr, warp tile 64x64, BK=64 ------
// C[M,N] = A[M,K] (K-major) * B[K,N] (N-major), batched over blockIdx.z.
// CTA 128x128, BK=64 (4 k16 phases/iter -> one wait+sync per 64-K),
// 3-stage cp.async, 2 CTAs/SM, 4 warps in 2x2, frag double-buffering.
// 256-reg cap (128 thr, occ 2): acc 128 + frags 64 + addressing fits.
#define STAGES 3
#define BK 64
#define TILE_M 128
#define TILE_N 128
#define NTHREADS 128
#define AROWB 144                    // A smem: 128B data + 16 pad per row (128 rows)
#define BROWB 272                    // B smem: 256B data + 16 pad per k-row (64 rows)
#define STG_A (TILE_M * AROWB)       // 18432 B
#define STG_B (BK * BROWB)           // 17408 B
#define SM_TOTAL (STAGES * (STG_A + STG_B))   // 107520 B -> 2 CTAs/SM

#define LDM_A(dst, base, p) do {                                              \
    _Pragma("unroll")                                                         \
    for (int _mt = 0; _mt < 4; _mt++)                                         \
        ldmx4((dst)[_mt], (base) + a_lm + _mt * (16 * AROWB) + (p) * 32);     \
} while (0)
#define LDM_B(dst, base, p) do {                                              \
    _Pragma("unroll")                                                         \
    for (int _np = 0; _np < 4; _np++)                                         \
        ldmx4t((dst)[_np], (base) + b_lm + (p) * (16 * BROWB) + _np * 32);    \
} while (0)
#define MMA_ALL(af, bf) do {                                                  \
    _Pragma("unroll")                                                         \
    for (int _mt = 0; _mt < 4; _mt++) {                                       \
        _Pragma("unroll")                                                     \
        for (int _nt = 0; _nt < 8; _nt++) {                                   \
            const uint32_t* _b = (bf)[_nt >> 1];                              \
            mma_f16(acc[_mt][_nt], (af)[_mt][0], (af)[_mt][1],                \
                    (af)[_mt][2], (af)[_mt][3],                               \
                    (_nt & 1) ? _b[2] : _b[0], (_nt & 1) ? _b[3] : _b[1]);    \
        }                                                                     \
    }                                                                         \
} while (0)

// Fill one stage: A 1024 chunks (8/thread), B 1024 chunks (8/thread).
// Chunk j offsets are base + j*const (tid+128j keeps low addressing bits).
#define FILL_STAGE(ao, bo, ka) do {                                           \
    const __half* _ap = Ag + a_o0 + (uint32_t)(ka);                           \
    const __half* _bp = Bg + b_o0 + (uint32_t)(ka) * (uint32_t)ldb;           \
    uint32_t _ad = (ao) + a_d0, _bd = (bo) + b_d0;                            \
    _Pragma("unroll")                                                         \
    for (int _j = 0; _j < 8; _j++) {                                          \
        cp_async16(_ad, _ap); _ad += 16 * AROWB; _ap += lda16;                \
    }                                                                         \
    _Pragma("unroll")                                                         \
    for (int _j = 0; _j < 8; _j++) {                                          \
        cp_async16(_bd, _bp); _bd += 8 * BROWB; _bp += ldb8;                  \
    }                                                                         \
} while (0)

template<bool RELU, bool OUT_HALF>
__global__ __launch_bounds__(NTHREADS, 2)
void gemm_f16_mma(const __half* __restrict__ A, const __half* __restrict__ B,
                  void* __restrict__ Cv,
                  int K, int lda, int ldb, int ldc,
                  long long sA, long long sB, long long sC)
{
    extern __shared__ char smem[];
    const uint32_t a_base = smem_u32(smem);
    const uint32_t b_base = a_base + STAGES * STG_A;

    const int tid = threadIdx.x;
    const int wid = tid >> 5;
    const int lane = tid & 31;
    const int lq = lane >> 2;
    const int lr = lane & 3;
    const int warpM = wid & 1;     // 0..1 (64 rows each)
    const int warpN = wid >> 1;    // 0..1 (64 cols each)

    const long long e = blockIdx.z;
    const __half* Ag = A + e * sA + (long long)blockIdx.y * TILE_M * lda;
    const __half* Bg = B + e * sB + (long long)blockIdx.x * TILE_N;   // B: [K,N]

    // cp.async base offsets (chunk 0 of this thread)
    const uint32_t a_d0 = (uint32_t)(tid >> 3) * AROWB + (uint32_t)(tid & 7) * 16;
    const uint32_t a_o0 = (uint32_t)((tid >> 3) * lda + (tid & 7) * 8);
    const uint32_t b_d0 = (uint32_t)(tid >> 4) * BROWB + (uint32_t)(tid & 15) * 16;
    const uint32_t b_o0 = (uint32_t)((tid >> 4) * ldb + (tid & 15) * 8);
    const uint32_t lda16 = 16u * (uint32_t)lda;
    const uint32_t ldb8  = 8u * (uint32_t)ldb;

    // ldmatrix source offsets (strides ≡16 mod 128 -> conflict-free)
    const uint32_t a_lm = (uint32_t)(warpM * 64 + (lane & 15)) * AROWB + ((lane >> 4) & 1) * 16;
    const uint32_t b_lm = (uint32_t)(lane & 15) * BROWB
                        + (uint32_t)(warpN * 64 + ((lane >> 4) & 1) * 8) * 2;

    const int niters = K / BK;

    // prologue: stages 0,1
    FILL_STAGE(a_base, b_base, 0);
    CP_COMMIT();
    FILL_STAGE(a_base + STG_A, b_base + STG_B, BK);
    CP_COMMIT();

    float acc[4][8][4];                           // 128 accumulators
    #pragma unroll
    for (int i = 0; i < 4; i++)
        #pragma unroll
        for (int j = 0; j < 8; j++)
            #pragma unroll
            for (int k = 0; k < 4; k++)
                acc[i][j][k] = 0.0f;

    uint32_t afX[4][4], bfX[4][4];   // even phases
    uint32_t afY[4][4], bfY[4][4];   // odd phases

    // wait stage 0, load phase-0 frags
    CP_WAIT1();
    __syncthreads();
    uint32_t As = a_base, Bs = b_base;           // current stage
    uint32_t pA = a_base + 2 * STG_A;            // prefetch slot (stage 2)
    uint32_t pB = b_base + 2 * STG_B;
    LDM_A(afX, As, 0);
    LDM_B(bfX, Bs, 0);

    int pre = STAGES - 1;

    for (int it = 0; it < niters; it++) {
        // ---- phase 0: load p1 frags, prefetch gmem stage it+2, MMA p0 ----
        LDM_A(afY, As, 1);
        LDM_B(bfY, Bs, 1);
        if (pre < niters) {
            FILL_STAGE(pA, pB, pre * BK);
            pA += STG_A; if (pA == a_base + STAGES * STG_A) pA = a_base;
            pB += STG_B; if (pB == b_base + STAGES * STG_B) pB = b_base;
        }
        CP_COMMIT();
        pre++;
        MMA_ALL(afX, bfX);

        // ---- phase 1: load p2, MMA p1 ----
        LDM_A(afX, As, 2);
        LDM_B(bfX, Bs, 2);
        MMA_ALL(afY, bfY);

        // ---- phase 2: load p3, MMA p2 ----
        LDM_A(afY, As, 3);
        LDM_B(bfY, Bs, 3);
        MMA_ALL(afX, bfX);

        // ---- phase 3: advance stage, load next p0, MMA p3 ----
        if (it + 1 < niters) {
            CP_WAIT1();          // stage it+1 landed (<=1 group outstanding)
            __syncthreads();     // cross-thread visibility + WAR for recycled slot
            As += STG_A; if (As == a_base + STAGES * STG_A) As = a_base;
            Bs += STG_B; if (Bs == b_base + STAGES * STG_B) Bs = b_base;
            LDM_A(afX, As, 0);
            LDM_B(bfX, Bs, 0);
        }
        MMA_ALL(afY, bfY);
    }

    // ---- epilogue ----
    #pragma unroll
    for (int mt = 0; mt < 4; mt++) {
        const int r0 = blockIdx.y * TILE_M + warpM * 64 + mt * 16 + lq;
        #pragma unroll
        for (int nt = 0; nt < 8; nt++) {
            const int c0 = blockIdx.x * TILE_N + warpN * 64 + nt * 8 + 2 * lr;
            float v0 = acc[mt][nt][0], v1 = acc[mt][nt][1];
            float v2 = acc[mt][nt][2], v3 = acc[mt][nt][3];
            if (RELU) {
                v0 = fmaxf(v0, 0.0f); v1 = fmaxf(v1, 0.0f);
                v2 = fmaxf(v2, 0.0f); v3 = fmaxf(v3, 0.0f);
            }
            if (OUT_HALF) {
                __half* C = (__half*)Cv + e * sC;
                *reinterpret_cast<__half2*>(C + (long long)r0 * ldc + c0)       = __floats2half2_rn(v0, v1);
                *reinterpret_cast<__half2*>(C + (long long)(r0 + 8) * ldc + c0) = __floats2half2_rn(v2, v3);
            } else {
                float* C = (float*)Cv + e * sC;
                *reinterpret_cast<float2*>(C + (long long)r0 * ldc + c0)       = make_float2(v0, v1);
                *reinterpret_cast<float2*>(C + (long long)(r0 + 8) * ldc + c0) = make_float2(v2, v3);
            }
        }
    }
}

// ---------------- launch ----------------
extern "C" void kernel_launch(void* const* d_in, const int* in_sizes, int n_in,
                              void* d_out, int out_size)
{
    const float* X  = (const float*)d_in[0];
    const float* W1 = (const float*)d_in[2];
    const float* W2 = (const float*)d_in[3];
    float* Y = (float*)d_out;

    __half *Xh, *W1h, *W2h, *Hh;
    cudaGetSymbolAddress((void**)&Xh,  g_Xh);
    cudaGetSymbolAddress((void**)&W1h, g_W1h);
    cudaGetSymbolAddress((void**)&W2h, g_W2h);
    cudaGetSymbolAddress((void**)&Hh,  g_Hh);

    static bool attr_set = false;
    if (!attr_set) {
        cudaFuncSetAttribute(gemm_f16_mma<true, true>,   cudaFuncAttributeMaxDynamicSharedMemorySize, SM_TOTAL);
        cudaFuncSetAttribute(gemm_f16_mma<false, false>, cudaFuncAttributeMaxDynamicSharedMemorySize, SM_TOTAL);
        attr_set = true;
    }

    // casts
    {
        size_t n4 = (size_t)NE * NC * ND / 4;
        f32_to_f16_kernel<<<(unsigned)((n4 + 255) / 256), 256>>>(X, Xh, n4);
    }
    {
        size_t n4 = (size_t)NE * ND * NF / 4;
        f32_to_f16_kernel<<<(unsigned)((n4 + 255) / 256), 256>>>(W1, W1h, n4);
    }
    {
        size_t n4 = (size_t)NE * NF * ND / 4;
        f32_to_f16_kernel<<<(unsigned)((n4 + 255) / 256), 256>>>(W2, W2h, n4);
    }

    // GEMM1: H = relu(Xh @ W1h); M=C, N=F, K=D; ldb=NF
    {
        dim3 g(NF / TILE_N, NC / TILE_M, NE);
        gemm_f16_mma<true, true><<<g, NTHREADS, SM_TOTAL>>>(
            Xh, W1h, Hh,
            ND, ND, NF, NF,
            (long long)NC * ND, (long long)ND * NF, (long long)NC * NF);
    }
    // GEMM2: Y = H @ W2h; M=C, N=D, K=F; ldb=ND
    {
        dim3 g(ND / TILE_N, NC / TILE_M, NE);
        gemm_f16_mma<false, false><<<g, NTHREADS, SM_TOTAL>>>(
            Hh, W2h, Y,
            NF, NF, ND, ND,
            (long long)NC * NF, (long long)NF * ND, (long long)NC * ND);
    }
}